// round 12
// baseline (speedup 1.0000x reference)
#include <cuda_runtime.h>
#include <cstdint>

// LTC scan, round 12.
// R11 audit: k-half split halved LDS instructions but NOT wavefronts — the two
// 16B halves live 256B apart (2 lines => 2 wavefronts per LDS.128). L1 51% =
// co-saturation with fma.
// R12: 16B-INTERLEAVED k-halves in shared: posn(k)=8*((k&63)>>2)+4*(k>>6)+(k&3)
// => even/odd lanes read 32B consecutive => 1 wavefront per LDS. Per-row loads
// (no mixed rows per instruction); mine/other via 4 ALU SELs (R9-proven, no
// spills). add.rn.f32x2 pair-merge before f2sum shortens the tail.
// Same interleave treatment applied to xin_kernel (breaks its L1/fma co-sat).

#define Bsz 512
#define Ssz 512
#define Dsz 128
#define Hsz 128
#define UNFOLDS 6
#define SROW 132      // padded row stride (floats): 132*4=528B, 16B-aligned, odd 16B count

typedef unsigned long long ull;

__device__ float g_xin[(size_t)Bsz * Ssz * Hsz];   // [b][s][h] scratch

__device__ __forceinline__ ull ffma2(ull a, ull b, ull c) {
    ull d;
    asm("fma.rn.f32x2 %0, %1, %2, %3;" : "=l"(d) : "l"(a), "l"(b), "l"(c));
    return d;
}

__device__ __forceinline__ ull addf2(ull a, ull b) {
    ull d;
    asm("add.rn.f32x2 %0, %1, %2;" : "=l"(d) : "l"(a), "l"(b));
    return d;
}

__device__ __forceinline__ float f2sum(ull v) {
    float lo, hi;
    asm("mov.b64 {%0, %1}, %2;" : "=f"(lo), "=f"(hi) : "l"(v));
    return lo + hi;
}

__device__ __forceinline__ float ftanh(float s) {
    float y;
    asm("tanh.approx.f32 %0, %1;" : "=f"(y) : "f"(s));   // MUFU.TANH
    return y;
}

// interleaved position of logical column k within a 128-float row
__device__ __forceinline__ int posn(int k) {
    return 8 * ((k & 63) >> 2) + 4 * (k >> 6) + (k & 3);
}

// ---------------------------------------------------------------------------
// Kernel 1: xin[b,s,j] = sum_d x[b,s,d] * W_in[j,d] + b_in[j]
// Thread (p = tid>>1, hf = tid&1): units j0=2p, 2p+1 over k-half 64hf..64hf+63,
// 4 (b,s)-rows per chunk; cross-half combine via SHFL.XOR(1); each lane
// finalizes rows {2hf, 2hf+1}. x staged interleaved => 1-wavefront dot loads.
// ---------------------------------------------------------------------------
__global__ void __launch_bounds__(128, 2)
xin_kernel(const float* __restrict__ x,
           const float* __restrict__ W_in,
           const float* __restrict__ b_in)
{
    __shared__ float xs[2][4][SROW];

    const int tid = threadIdx.x;
    const int p   = tid >> 1;
    const int hf  = tid & 1;
    const int j0  = 2 * p;
    const int fpos = posn(tid);          // staging position for column tid

    // W_in rows j0, j0+1, cols [64hf, 64hf+64): 128 floats in registers.
    ull wiA[32], wiB[32];
    {
        const ulonglong2* wpA = (const ulonglong2*)(W_in + (size_t)j0 * Dsz + 64 * hf);
        const ulonglong2* wpB = (const ulonglong2*)(W_in + (size_t)(j0 + 1) * Dsz + 64 * hf);
        #pragma unroll
        for (int c = 0; c < 16; ++c) {
            ulonglong2 vA = wpA[c];
            ulonglong2 vB = wpB[c];
            wiA[2 * c] = vA.x;  wiA[2 * c + 1] = vA.y;
            wiB[2 * c] = vB.x;  wiB[2 * c + 1] = vB.y;
        }
    }
    const float biA = b_in[j0];
    const float biB = b_in[j0 + 1];

    const int m0 = blockIdx.x * 128;

    float xf[4];
    #pragma unroll
    for (int r = 0; r < 4; ++r)
        xf[r] = x[(size_t)(m0 + r) * Dsz + tid];

    #pragma unroll 1
    for (int ch = 0; ch < 32; ++ch) {
        float (*xb)[SROW] = xs[ch & 1];
        #pragma unroll
        for (int r = 0; r < 4; ++r)
            xb[r][fpos] = xf[r];
        __syncthreads();

        if (ch < 31) {
            #pragma unroll
            for (int r = 0; r < 4; ++r)
                xf[r] = x[(size_t)(m0 + (ch + 1) * 4 + r) * Dsz + tid];
        }

        // dot: 2 units x 4 rows over my k-half; loads interleaved (1 wavefront)
        ull aA0 = 0ull, aA1 = 0ull, aA2 = 0ull, aA3 = 0ull;   // unit j0, rows 0..3
        ull aB0 = 0ull, aB1 = 0ull, aB2 = 0ull, aB3 = 0ull;   // unit j0+1
        const float* xr = &xb[0][4 * hf];
        #pragma unroll
        for (int c = 0; c < 16; ++c) {
            ulonglong2 v0 = *(const ulonglong2*)(xr + 0 * SROW + 8 * c);
            ulonglong2 v1 = *(const ulonglong2*)(xr + 1 * SROW + 8 * c);
            ulonglong2 v2 = *(const ulonglong2*)(xr + 2 * SROW + 8 * c);
            ulonglong2 v3 = *(const ulonglong2*)(xr + 3 * SROW + 8 * c);
            aA0 = ffma2(wiA[2 * c], v0.x, aA0);  aB0 = ffma2(wiB[2 * c], v0.x, aB0);
            aA0 = ffma2(wiA[2 * c + 1], v0.y, aA0);  aB0 = ffma2(wiB[2 * c + 1], v0.y, aB0);
            aA1 = ffma2(wiA[2 * c], v1.x, aA1);  aB1 = ffma2(wiB[2 * c], v1.x, aB1);
            aA1 = ffma2(wiA[2 * c + 1], v1.y, aA1);  aB1 = ffma2(wiB[2 * c + 1], v1.y, aB1);
            aA2 = ffma2(wiA[2 * c], v2.x, aA2);  aB2 = ffma2(wiB[2 * c], v2.x, aB2);
            aA2 = ffma2(wiA[2 * c + 1], v2.y, aA2);  aB2 = ffma2(wiB[2 * c + 1], v2.y, aB2);
            aA3 = ffma2(wiA[2 * c], v3.x, aA3);  aB3 = ffma2(wiB[2 * c], v3.x, aB3);
            aA3 = ffma2(wiA[2 * c + 1], v3.y, aA3);  aB3 = ffma2(wiB[2 * c + 1], v3.y, aB3);
        }
        const float pA0 = f2sum(aA0), pA1 = f2sum(aA1), pA2 = f2sum(aA2), pA3 = f2sum(aA3);
        const float pB0 = f2sum(aB0), pB1 = f2sum(aB1), pB2 = f2sum(aB2), pB3 = f2sum(aB3);

        // I finalize rows {2hf, 2hf+1}; send the other pair of rows.
        const float keepA0 = hf ? pA2 : pA0, keepA1 = hf ? pA3 : pA1;
        const float sendA0 = hf ? pA0 : pA2, sendA1 = hf ? pA1 : pA3;
        const float keepB0 = hf ? pB2 : pB0, keepB1 = hf ? pB3 : pB1;
        const float sendB0 = hf ? pB0 : pB2, sendB1 = hf ? pB1 : pB3;
        const float recvA0 = __shfl_xor_sync(0xffffffffu, sendA0, 1);
        const float recvA1 = __shfl_xor_sync(0xffffffffu, sendA1, 1);
        const float recvB0 = __shfl_xor_sync(0xffffffffu, sendB0, 1);
        const float recvB1 = __shfl_xor_sync(0xffffffffu, sendB1, 1);

        const int m = m0 + ch * 4 + 2 * hf;
        float2 o0, o1;
        o0.x = keepA0 + recvA0 + biA;  o0.y = keepB0 + recvB0 + biB;
        o1.x = keepA1 + recvA1 + biA;  o1.y = keepB1 + recvB1 + biB;
        *(float2*)&g_xin[(size_t)m * Hsz + j0]       = o0;
        *(float2*)&g_xin[(size_t)(m + 1) * Hsz + j0] = o1;
    }
}

// ---------------------------------------------------------------------------
// Kernel 2: sequential scan. grid 256 x 128 threads, 2 rows/CTA, 2 CTAs/SM.
// Thread (p, hf): units j0=2p, 2p+1 over interleaved k-half; owns states
// (j0,row hf),(j0+1,row hf). 1 __syncthreads/unfold, shfl combine, MUFU.TANH.
// ---------------------------------------------------------------------------
__global__ void __launch_bounds__(128, 2)
ltc_main(const float* __restrict__ W_r,
         const float* __restrict__ b_r,
         const float* __restrict__ W_fc,
         const float* __restrict__ b_fc,
         float* __restrict__ out)
{
    __shared__ float hs[2][2][SROW];   // [buf][row][interleaved k]
    __shared__ float red[2][64];

    const int tid  = threadIdx.x;
    const int p    = tid >> 1;
    const int hf   = tid & 1;
    const int j0   = 2 * p;
    const int base = blockIdx.x * 2;
    const int offP = hf * SROW + posn(j0);      // publish offset (row hf, cols j0,j0+1)

    // W_r rows j0, j0+1, cols [64hf, 64hf+64): 128 floats in registers.
    ull wA[32], wB[32];
    {
        const ulonglong2* wpA = (const ulonglong2*)(W_r + (size_t)j0 * Hsz + 64 * hf);
        const ulonglong2* wpB = (const ulonglong2*)(W_r + (size_t)(j0 + 1) * Hsz + 64 * hf);
        #pragma unroll
        for (int c = 0; c < 16; ++c) {
            ulonglong2 vA = wpA[c];
            ulonglong2 vB = wpB[c];
            wA[2 * c] = vA.x;  wA[2 * c + 1] = vA.y;
            wB[2 * c] = vB.x;  wB[2 * c + 1] = vB.y;
        }
    }

    const float2 bb2 = *(const float2*)&b_r[j0];

    float h0 = 0.f, h1 = 0.f;             // (j0, row hf), (j0+1, row hf)

    hs[0][0][offP]     = 0.f;             // bootstrap publish into buffer 0
    hs[0][0][offP + 1] = 0.f;

    const size_t xi = (size_t)(base + hf) * Ssz * Hsz + j0;
    float2 xf = *(const float2*)&g_xin[xi];

    #pragma unroll 1
    for (int t = 0; t < Ssz; ++t) {
        const float xinA = xf.x + bb2.x;
        const float xinB = xf.y + bb2.y;
        const int tn = (t + 1 < Ssz) ? (t + 1) : t;    // branchless prefetch
        xf = *(const float2*)&g_xin[xi + (size_t)tn * Hsz];

        #pragma unroll 1
        for (int u = 0; u < UNFOLDS; ++u) {
            const float* hb = hs[u & 1][0];        // read buffer base
            float*       hn = hs[(u + 1) & 1][0];  // write buffer base
            __syncthreads();

            // dot: units j0, j0+1 x rows {0,1}; per-row loads, interleaved
            // k-halves => even/odd lanes read 32B consecutive => 1 wavefront.
            ull a0 = 0ull, a1 = 0ull, b0 = 0ull, b1 = 0ull;   // row 0
            ull c0 = 0ull, c1 = 0ull, d0 = 0ull, d1 = 0ull;   // row 1
            const float* r0p = hb + 4 * hf;
            const float* r1p = hb + SROW + 4 * hf;
            #pragma unroll     // full unroll: wA/wB must stay in registers
            for (int c = 0; c < 16; ++c) {
                ulonglong2 v0 = *(const ulonglong2*)(r0p + 8 * c);
                ulonglong2 v1 = *(const ulonglong2*)(r1p + 8 * c);
                a0 = ffma2(wA[2 * c],     v0.x, a0);
                b0 = ffma2(wB[2 * c],     v0.x, b0);   // v0.x reused
                a1 = ffma2(wA[2 * c + 1], v0.y, a1);
                b1 = ffma2(wB[2 * c + 1], v0.y, b1);   // v0.y reused
                c0 = ffma2(wA[2 * c],     v1.x, c0);
                d0 = ffma2(wB[2 * c],     v1.x, d0);   // v1.x reused
                c1 = ffma2(wA[2 * c + 1], v1.y, c1);
                d1 = ffma2(wB[2 * c + 1], v1.y, d1);   // v1.y reused
            }
            const float PaR0 = f2sum(addf2(a0, a1));   // (j0,   row0)
            const float PbR0 = f2sum(addf2(b0, b1));   // (j0+1, row0)
            const float PaR1 = f2sum(addf2(c0, c1));   // (j0,   row1)
            const float PbR1 = f2sum(addf2(d0, d1));   // (j0+1, row1)

            // my row = hf; send the other row's partials to lane^1.
            const float keepA = hf ? PaR1 : PaR0;
            const float keepB = hf ? PbR1 : PbR0;
            const float sendA = hf ? PaR0 : PaR1;
            const float sendB = hf ? PbR0 : PbR1;
            const float recvA = __shfl_xor_sync(0xffffffffu, sendA, 1);
            const float recvB = __shfl_xor_sync(0xffffffffu, sendB, 1);

            h0 = 0.9f * h0 + 0.1f * ftanh(keepA + recvA + xinA);
            h1 = 0.9f * h1 + 0.1f * ftanh(keepB + recvB + xinB);

            float2 st;  st.x = h0;  st.y = h1;
            *(float2*)(hn + offP) = st;
        }
    }

    // out[b] = b_fc + sum_j h[b][j] * W_fc[j]
    __syncthreads();
    {
        const float2 wfc2 = *(const float2*)&W_fc[j0];
        red[hf][p] = h0 * wfc2.x + h1 * wfc2.y;
    }
    __syncthreads();

    const int wid = tid >> 5, lane = tid & 31;
    if (wid < 2) {
        float s = red[wid][lane] + red[wid][lane + 32];
        #pragma unroll
        for (int d = 16; d > 0; d >>= 1)
            s += __shfl_xor_sync(0xffffffffu, s, d);
        if (lane == 0)
            out[base + wid] = s + b_fc[0];
    }
}

extern "C" void kernel_launch(void* const* d_in, const int* in_sizes, int n_in,
                              void* d_out, int out_size)
{
    const float* x    = (const float*)d_in[0];
    const float* W_in = (const float*)d_in[1];
    const float* b_in = (const float*)d_in[2];
    const float* W_r  = (const float*)d_in[3];
    const float* b_r  = (const float*)d_in[4];
    const float* W_fc = (const float*)d_in[5];
    const float* b_fc = (const float*)d_in[6];
    float* out = (float*)d_out;

    xin_kernel<<<(Bsz * Ssz) / 128, 128>>>(x, W_in, b_in);
    ltc_main<<<Bsz / 2, 128>>>(W_r, b_r, W_fc, b_fc, out);
}

// round 13
// speedup vs baseline: 1.0291x; 1.0291x over previous
#include <cuda_runtime.h>
#include <cstdint>

// LTC scan, round 13.
// R12 post-mortem: interleave was neutral-negative (L1% tracks LDS instruction
// count, not line splits); scan reverted to R11 exact (1403us plateau,
// structurally pinned by RF capacity: W must be register-split across 4 warps
// => shared h exchange + 1 BAR/unfold is forced).
// R13 work item: xin_kernel — 8 rows/chunk (barriers halved), unit-pair x
// k-half layout, per-thread finalization of 4 rows (tail per row halved).

#define Bsz 512
#define Ssz 512
#define Dsz 128
#define Hsz 128
#define UNFOLDS 6
#define HSTRIDE 136   // scan: 128 + 4 (pad at k=64) + 4 (row-stride bank shift)
#define XROW 132      // xin: padded row stride

typedef unsigned long long ull;

__device__ float g_xin[(size_t)Bsz * Ssz * Hsz];   // [b][s][h] scratch

__device__ __forceinline__ ull ffma2(ull a, ull b, ull c) {
    ull d;
    asm("fma.rn.f32x2 %0, %1, %2, %3;" : "=l"(d) : "l"(a), "l"(b), "l"(c));
    return d;
}

__device__ __forceinline__ float f2sum(ull v) {
    float lo, hi;
    asm("mov.b64 {%0, %1}, %2;" : "=f"(lo), "=f"(hi) : "l"(v));
    return lo + hi;
}

__device__ __forceinline__ float ftanh(float s) {
    float y;
    asm("tanh.approx.f32 %0, %1;" : "=f"(y) : "f"(s));   // MUFU.TANH
    return y;
}

// ---------------------------------------------------------------------------
// Kernel 1: xin[b,s,j] = sum_d x[b,s,d] * W_in[j,d] + b_in[j]
// 128 threads; thread (p = tid>>1, hf = tid&1): units j0=2p, 2p+1 over k-half
// [64hf, 64hf+64). 8 (b,s)-rows per chunk, 16 chunks per CTA (128 rows).
// Cross-half combine via SHFL.XOR(1); lane finalizes rows [4hf, 4hf+4).
// ---------------------------------------------------------------------------
__global__ void __launch_bounds__(128, 2)
xin_kernel(const float* __restrict__ x,
           const float* __restrict__ W_in,
           const float* __restrict__ b_in)
{
    __shared__ float xs[2][8][XROW];

    const int tid = threadIdx.x;
    const int p   = tid >> 1;
    const int hf  = tid & 1;
    const int j0  = 2 * p;

    // W_in rows j0, j0+1, cols [64hf, 64hf+64): 128 floats in registers.
    ull wiA[32], wiB[32];
    {
        const ulonglong2* wpA = (const ulonglong2*)(W_in + (size_t)j0 * Dsz + 64 * hf);
        const ulonglong2* wpB = (const ulonglong2*)(W_in + (size_t)(j0 + 1) * Dsz + 64 * hf);
        #pragma unroll
        for (int c = 0; c < 16; ++c) {
            ulonglong2 vA = wpA[c];
            ulonglong2 vB = wpB[c];
            wiA[2 * c] = vA.x;  wiA[2 * c + 1] = vA.y;
            wiB[2 * c] = vB.x;  wiB[2 * c + 1] = vB.y;
        }
    }
    const float biA = b_in[j0];
    const float biB = b_in[j0 + 1];

    const int m0 = blockIdx.x * 128;

    float xf[8];
    #pragma unroll
    for (int r = 0; r < 8; ++r)
        xf[r] = x[(size_t)(m0 + r) * Dsz + tid];

    #pragma unroll 1
    for (int ch = 0; ch < 16; ++ch) {
        float (*xb)[XROW] = xs[ch & 1];
        #pragma unroll
        for (int r = 0; r < 8; ++r)
            xb[r][tid] = xf[r];
        __syncthreads();

        if (ch < 15) {
            #pragma unroll
            for (int r = 0; r < 8; ++r)
                xf[r] = x[(size_t)(m0 + (ch + 1) * 8 + r) * Dsz + tid];
        }

        // dot: 2 units x 8 rows over my k-half (each 16B x-load feeds 4 FFMA2)
        ull aA[8], aB[8];
        #pragma unroll
        for (int r = 0; r < 8; ++r) { aA[r] = 0ull; aB[r] = 0ull; }
        const float* xr = &xb[0][64 * hf];
        #pragma unroll
        for (int c = 0; c < 16; ++c) {
            #pragma unroll
            for (int r = 0; r < 8; ++r) {
                ulonglong2 v = *(const ulonglong2*)(xr + r * XROW + 4 * c);
                aA[r] = ffma2(wiA[2 * c],     v.x, aA[r]);
                aB[r] = ffma2(wiB[2 * c],     v.x, aB[r]);   // v.x reused
                aA[r] = ffma2(wiA[2 * c + 1], v.y, aA[r]);
                aB[r] = ffma2(wiB[2 * c + 1], v.y, aB[r]);   // v.y reused
            }
        }

        float pA[8], pB[8];
        #pragma unroll
        for (int r = 0; r < 8; ++r) { pA[r] = f2sum(aA[r]); pB[r] = f2sum(aB[r]); }

        // Lane finalizes rows [4hf, 4hf+4); sends the other 4 rows' partials.
        #pragma unroll
        for (int rr = 0; rr < 4; ++rr) {
            const int rk = 4 * hf + rr;          // row I keep
            const int rs = 4 * (hf ^ 1) + rr;    // row I send
            const float recvA = __shfl_xor_sync(0xffffffffu, pA[rs], 1);
            const float recvB = __shfl_xor_sync(0xffffffffu, pB[rs], 1);
            float2 o;
            o.x = pA[rk] + recvA + biA;
            o.y = pB[rk] + recvB + biB;
            *(float2*)&g_xin[(size_t)(m0 + ch * 8 + rk) * Hsz + j0] = o;
        }
    }
}

// ---------------------------------------------------------------------------
// Kernel 2: sequential scan — R11 verbatim (measured 1403us).
// grid 256 x 128 threads, 2 rows/CTA, 2 CTAs/SM. Thread (p, hf): units
// j0=2p, 2p+1 over k-half [64hf,64hf+64); owns states (j0,row hf),(j0+1,row hf).
// 1 __syncthreads/unfold, shfl combine, MUFU.TANH, scalar mine/other offsets.
// ---------------------------------------------------------------------------
__global__ void __launch_bounds__(128, 2)
ltc_main(const float* __restrict__ W_r,
         const float* __restrict__ b_r,
         const float* __restrict__ W_fc,
         const float* __restrict__ b_fc,
         float* __restrict__ out)
{
    __shared__ float hs[2][2][HSTRIDE];   // [buf][row][padded k]
    __shared__ float red[2][64];

    const int tid  = threadIdx.x;
    const int p    = tid >> 1;
    const int hf   = tid & 1;
    const int j0   = 2 * p;
    const int base = blockIdx.x * 2;
    const int koff = hf * 68;                   // 64 floats + 4-float pad at k=64
    const int jph  = j0 + (j0 >= 64 ? 4 : 0);   // padded publish index
    const int rowM = hf * HSTRIDE;
    const int rowO = (hf ^ 1) * HSTRIDE;
    const int offM = rowM + koff;
    const int offO = rowO + koff;
    const int offP = rowM + jph;

    ull wA[32], wB[32];
    {
        const ulonglong2* wpA = (const ulonglong2*)(W_r + (size_t)j0 * Hsz + 64 * hf);
        const ulonglong2* wpB = (const ulonglong2*)(W_r + (size_t)(j0 + 1) * Hsz + 64 * hf);
        #pragma unroll
        for (int c = 0; c < 16; ++c) {
            ulonglong2 vA = wpA[c];
            ulonglong2 vB = wpB[c];
            wA[2 * c] = vA.x;  wA[2 * c + 1] = vA.y;
            wB[2 * c] = vB.x;  wB[2 * c + 1] = vB.y;
        }
    }

    const float2 bb2 = *(const float2*)&b_r[j0];

    float h0 = 0.f, h1 = 0.f;

    hs[0][0][offP]     = 0.f;
    hs[0][0][offP + 1] = 0.f;

    const size_t xi = (size_t)(base + hf) * Ssz * Hsz + j0;
    float2 xf = *(const float2*)&g_xin[xi];

    #pragma unroll 1
    for (int t = 0; t < Ssz; ++t) {
        const float xinA = xf.x + bb2.x;
        const float xinB = xf.y + bb2.y;
        if (t + 1 < Ssz)
            xf = *(const float2*)&g_xin[xi + (size_t)(t + 1) * Hsz];

        #pragma unroll 1
        for (int u = 0; u < UNFOLDS; ++u) {
            const float* hb = hs[u & 1][0];
            float*       hn = hs[(u + 1) & 1][0];
            __syncthreads();

            ull a0 = 0ull, a1 = 0ull, b0 = 0ull, b1 = 0ull;   // my row
            ull c0 = 0ull, c1 = 0ull, d0 = 0ull, d1 = 0ull;   // other row
            #pragma unroll
            for (int c = 0; c < 16; ++c) {
                ulonglong2 vM = *(const ulonglong2*)(hb + offM + 4 * c);
                ulonglong2 vO = *(const ulonglong2*)(hb + offO + 4 * c);
                a0 = ffma2(wA[2 * c],     vM.x, a0);
                b0 = ffma2(wB[2 * c],     vM.x, b0);
                a1 = ffma2(wA[2 * c + 1], vM.y, a1);
                b1 = ffma2(wB[2 * c + 1], vM.y, b1);
                c0 = ffma2(wA[2 * c],     vO.x, c0);
                d0 = ffma2(wB[2 * c],     vO.x, d0);
                c1 = ffma2(wA[2 * c + 1], vO.y, c1);
                d1 = ffma2(wB[2 * c + 1], vO.y, d1);
            }
            const float PaM = f2sum(a0) + f2sum(a1);
            const float PbM = f2sum(b0) + f2sum(b1);
            const float PaO = f2sum(c0) + f2sum(c1);
            const float PbO = f2sum(d0) + f2sum(d1);

            const float recvA = __shfl_xor_sync(0xffffffffu, PaO, 1);
            const float recvB = __shfl_xor_sync(0xffffffffu, PbO, 1);

            h0 = 0.9f * h0 + 0.1f * ftanh(PaM + recvA + xinA);
            h1 = 0.9f * h1 + 0.1f * ftanh(PbM + recvB + xinB);

            float2 st;  st.x = h0;  st.y = h1;
            *(float2*)(hn + offP) = st;
        }
    }

    __syncthreads();
    {
        const float2 wfc2 = *(const float2*)&W_fc[j0];
        red[hf][p] = h0 * wfc2.x + h1 * wfc2.y;
    }
    __syncthreads();

    const int wid = tid >> 5, lane = tid & 31;
    if (wid < 2) {
        float s = red[wid][lane] + red[wid][lane + 32];
        #pragma unroll
        for (int d = 16; d > 0; d >>= 1)
            s += __shfl_xor_sync(0xffffffffu, s, d);
        if (lane == 0)
            out[base + wid] = s + b_fc[0];
    }
}

extern "C" void kernel_launch(void* const* d_in, const int* in_sizes, int n_in,
                              void* d_out, int out_size)
{
    const float* x    = (const float*)d_in[0];
    const float* W_in = (const float*)d_in[1];
    const float* b_in = (const float*)d_in[2];
    const float* W_r  = (const float*)d_in[3];
    const float* b_r  = (const float*)d_in[4];
    const float* W_fc = (const float*)d_in[5];
    const float* b_fc = (const float*)d_in[6];
    float* out = (float*)d_out;

    xin_kernel<<<(Bsz * Ssz) / 128, 128>>>(x, W_in, b_in);
    ltc_main<<<Bsz / 2, 128>>>(W_r, b_r, W_fc, b_fc, out);
}